// round 16
// baseline (speedup 1.0000x reference)
#include <cuda_runtime.h>
#include <cuda_bf16.h>
#include <stdint.h>

// Problem constants
#define NE 16384   // edges
// features [E,32,16], basis [E,16,44,16], w3 [45056,32], out [E,32,16]

// Intermediates
__device__ float g_H[NE * 32];        // radial MLP output, pre-rounded to tf32
// w3 pre-rounded to tf32, FRAGMENT-CONTIGUOUS layout:
//   idx = (((fc*16 + co_l)*2 + mt)*4 + q)*128 + lane*4 + v
//   (fc = f*2+c; co = c*16+co_l; ci = mt*16 + (v&1 ? g+8 : g);
//    m = q*8 + tg + (v&2 ? 4 : 0))
__device__ float g_w3p[45056 * 32];

// ---------------------------------------------------------------------------
// helpers
// ---------------------------------------------------------------------------
__device__ __forceinline__ uint32_t f2tf(float x) {
    uint32_t r;
    asm("cvt.rna.tf32.f32 %0, %1;" : "=r"(r) : "f"(x));
    return r;
}
__device__ __forceinline__ float f2tf_f(float x) {
    return __uint_as_float(f2tf(x));
}
__device__ __forceinline__ void mma8(float* d, const uint32_t* a, uint32_t b0, uint32_t b1) {
    asm volatile(
        "mma.sync.aligned.m16n8k8.row.col.f32.tf32.tf32.f32 "
        "{%0,%1,%2,%3}, {%4,%5,%6,%7}, {%8,%9}, {%0,%1,%2,%3};"
        : "+f"(d[0]), "+f"(d[1]), "+f"(d[2]), "+f"(d[3])
        : "r"(a[0]), "r"(a[1]), "r"(a[2]), "r"(a[3]), "r"(b0), "r"(b1));
}

// ---------------------------------------------------------------------------
// Kernel 0: pre-round w3 to tf32 into the fragment-contiguous layout (unchanged).
// ---------------------------------------------------------------------------
__global__ void w3p_kernel(const float* __restrict__ w3) {
    int idx  = blockIdx.x * 256 + threadIdx.x;   // 45056*32 = 1441792 total
    int v    = idx & 3;
    int lane = (idx >> 2) & 31;
    int q    = (idx >> 7) & 3;
    int mt   = (idx >> 9) & 1;
    int col  = (idx >> 10) & 15;   // co_l
    int fc   = idx >> 14;          // 0..87
    int f = fc >> 1, c = fc & 1;
    int g = lane >> 2, tg = lane & 3;
    int ci = mt * 16 + ((v & 1) ? g + 8 : g);
    int m  = q * 8 + tg + ((v & 2) ? 4 : 0);
    int co = c * 16 + col;
    g_w3p[idx] = f2tf_f(__ldg(&w3[(size_t)(co * 1408 + ci * 44 + f) * 32 + m]));
}

// ---------------------------------------------------------------------------
// Kernel 1: radial MLP (Linear->LN->ReLU->Linear->LN->ReLU) -> g_H (tf32-rounded)
// ---------------------------------------------------------------------------
__global__ void mlp_kernel(const float* __restrict__ x,
                           const float* __restrict__ w1, const float* __restrict__ b1,
                           const float* __restrict__ g1, const float* __restrict__ be1,
                           const float* __restrict__ w2, const float* __restrict__ b2,
                           const float* __restrict__ g2, const float* __restrict__ be2) {
    int e = blockIdx.x * blockDim.x + threadIdx.x;
    if (e >= NE) return;

    float xin[16];
#pragma unroll
    for (int j = 0; j < 16; j++) xin[j] = x[e * 16 + j];

    float h1[32];
#pragma unroll
    for (int m = 0; m < 32; m++) {
        float s = b1[m];
#pragma unroll
        for (int j = 0; j < 16; j++) s = fmaf(xin[j], w1[m * 16 + j], s);
        h1[m] = s;
    }
    float mu = 0.f;
#pragma unroll
    for (int m = 0; m < 32; m++) mu += h1[m];
    mu *= (1.0f / 32.0f);
    float var = 0.f;
#pragma unroll
    for (int m = 0; m < 32; m++) { float d = h1[m] - mu; var = fmaf(d, d, var); }
    var *= (1.0f / 32.0f);
    float inv = rsqrtf(var + 1e-5f);
#pragma unroll
    for (int m = 0; m < 32; m++)
        h1[m] = fmaxf((h1[m] - mu) * inv * g1[m] + be1[m], 0.0f);

    float h2[32];
#pragma unroll
    for (int m = 0; m < 32; m++) {
        float s = b2[m];
#pragma unroll
        for (int j = 0; j < 32; j++) s = fmaf(h1[j], w2[m * 32 + j], s);
        h2[m] = s;
    }
    mu = 0.f;
#pragma unroll
    for (int m = 0; m < 32; m++) mu += h2[m];
    mu *= (1.0f / 32.0f);
    var = 0.f;
#pragma unroll
    for (int m = 0; m < 32; m++) { float d = h2[m] - mu; var = fmaf(d, d, var); }
    var *= (1.0f / 32.0f);
    inv = rsqrtf(var + 1e-5f);
#pragma unroll
    for (int m = 0; m < 32; m++)
        g_H[e * 32 + m] = f2tf_f(fmaxf((h2[m] - mu) * inv * g2[m] + be2[m], 0.0f));
}

// ---------------------------------------------------------------------------
// Kernel 2: fused conv. CTA = 16 edges, 256 threads (8 warps), tf32 mma.
// 2 CTAs resident per SM (smem 108.8 KB, 128 regs/thread).
//
// smem (floats):
//   TMP [16e][16s][36ci]  @ 0      9280  (also prologue feat scratch spills into RW,
//                                          epilogue scratch)
//   RW0 [16e][16co][36ci] @ 9280   9280  (radial-weight chunk, buf c=0)
//   RW1                   @ 18560  9280  (buf c=1)
// total 27840 floats = 111360 B
// 2 __syncthreads per frequency iteration + 1 guarding the epilogue scratch.
// ---------------------------------------------------------------------------
#define TMP_OFF 0
#define RW_OFF  9280
#define RWSZ    9280
#define SMEM_BYTES (27840 * 4)

__global__ void __launch_bounds__(256, 2)
conv_kernel(const float* __restrict__ feat,
            const float* __restrict__ basis,
            float* __restrict__ out) {
    extern __shared__ float sm[];
    const int t    = threadIdx.x;
    const int wid  = t >> 5;      // 0..7
    const int lane = t & 31;
    const int g    = lane >> 2;   // 0..7
    const int tg   = lane & 3;    // 0..3
    const int e0   = blockIdx.x * 16;

    // ---- hoist H B-fragments (invariant over f and c): 16 regs ----
    uint32_t hB[4][2][2];
#pragma unroll
    for (int k = 0; k < 4; k++)
#pragma unroll
        for (int nt = 0; nt < 2; nt++) {
            hB[k][nt][0] = __float_as_uint(g_H[(size_t)(e0 + nt * 8 + g) * 32 + k * 8 + tg]);
            hB[k][nt][1] = __float_as_uint(g_H[(size_t)(e0 + nt * 8 + g) * 32 + k * 8 + tg + 4]);
        }

    // ---- stage features -> smem scratch (str-20 rows, conflict-free) ----
    {
        const float4* src = reinterpret_cast<const float4*>(feat + (size_t)e0 * 512);
#pragma unroll
        for (int j = 0; j < 8; j++) {
            int idx = t + j * 256;
            int e = idx >> 7, pos = (idx & 127) * 4;
            int r = pos >> 4, c0 = pos & 15;
            float4 v = src[idx];
            float* d = sm + e * 640 + r * 20 + c0;
            d[0] = v.x; d[1] = v.y; d[2] = v.z; d[3] = v.w;
        }
    }
    __syncthreads();

    // ---- hoist feature A-fragments (2 edges/warp): 32 regs ----
    uint32_t fa[2][2][2][4];   // [edge][mtile][kstep][frag]
#pragma unroll
    for (int le = 0; le < 2; le++) {
        const float* fs = sm + (wid * 2 + le) * 640;
#pragma unroll
        for (int mt = 0; mt < 2; mt++)
#pragma unroll
            for (int k = 0; k < 2; k++) {
                int r = mt * 16 + g, c = k * 8 + tg;
                fa[le][mt][k][0] = f2tf(fs[r * 20 + c]);
                fa[le][mt][k][1] = f2tf(fs[(r + 8) * 20 + c]);
                fa[le][mt][k][2] = f2tf(fs[r * 20 + c + 4]);
                fa[le][mt][k][3] = f2tf(fs[(r + 8) * 20 + c + 4]);
            }
    }
    __syncthreads();   // scratch regions reused below

    // output accumulators: [edge][co-chunk][s-ntile][frag]
    float acc[2][2][2][4];
#pragma unroll
    for (int a = 0; a < 2; a++)
#pragma unroll
        for (int c = 0; c < 2; c++)
#pragma unroll
            for (int n = 0; n < 2; n++)
#pragma unroll
                for (int r = 0; r < 4; r++) acc[a][c][n][r] = 0.f;

#pragma unroll 1
    for (int f = 0; f < 44; f++) {
        // ---- GEMM2: tmp_f[e] = feat_e @ basis_f_e (basis direct from gmem,
        //      all loads issued before any mma) ----
        float br[2][8];
#pragma unroll
        for (int le = 0; le < 2; le++) {
            const float* bb = basis + (size_t)(e0 + wid * 2 + le) * 11264 + f * 16;
#pragma unroll
            for (int nt = 0; nt < 2; nt++)
#pragma unroll
                for (int k = 0; k < 2; k++) {
                    br[le][nt * 4 + k * 2]     = __ldg(&bb[(k * 8 + tg) * 704 + nt * 8 + g]);
                    br[le][nt * 4 + k * 2 + 1] = __ldg(&bb[(k * 8 + tg + 4) * 704 + nt * 8 + g]);
                }
        }
#pragma unroll
        for (int le = 0; le < 2; le++) {
            float* tp = sm + TMP_OFF + (wid * 2 + le) * 580;
#pragma unroll
            for (int nt = 0; nt < 2; nt++) {
                uint32_t b00 = f2tf(br[le][nt * 4 + 0]), b01 = f2tf(br[le][nt * 4 + 1]);
                uint32_t b10 = f2tf(br[le][nt * 4 + 2]), b11 = f2tf(br[le][nt * 4 + 3]);
#pragma unroll
                for (int mt = 0; mt < 2; mt++) {
                    float c4[4] = {0.f, 0.f, 0.f, 0.f};
                    mma8(c4, fa[le][mt][0], b00, b01);
                    mma8(c4, fa[le][mt][1], b10, b11);
                    int sA = nt * 8 + 2 * tg, ciA = mt * 16 + g;
                    tp[sA * 36 + ciA]           = f2tf_f(c4[0]);
                    tp[(sA + 1) * 36 + ciA]     = f2tf_f(c4[1]);
                    tp[sA * 36 + ciA + 8]       = f2tf_f(c4[2]);
                    tp[(sA + 1) * 36 + ciA + 8] = f2tf_f(c4[3]);
                }
            }
        }

#pragma unroll
        for (int c = 0; c < 2; c++) {
            // ---- GEMM1: RW[co_l][ci][e]; warp covers co_l = wid and wid+8.
            //      A-fragments via coalesced LDG.128 from fragment-contiguous g_w3p ----
            float* Rwb = sm + RW_OFF + c * RWSZ;
#pragma unroll
            for (int ch = 0; ch < 2; ch++) {
                int co_l = wid + ch * 8;
                const float* wb = g_w3p + (((size_t)(f * 2 + c) * 16 + co_l) * 2) * 512;
#pragma unroll
                for (int mt = 0; mt < 2; mt++) {
                    const float4* W4 = reinterpret_cast<const float4*>(wb + mt * 512);
                    uint32_t ar[16];
#pragma unroll
                    for (int q = 0; q < 4; q++) {
                        float4 v = __ldg(&W4[q * 32 + lane]);
                        ar[q * 4 + 0] = __float_as_uint(v.x);
                        ar[q * 4 + 1] = __float_as_uint(v.y);
                        ar[q * 4 + 2] = __float_as_uint(v.z);
                        ar[q * 4 + 3] = __float_as_uint(v.w);
                    }
#pragma unroll
                    for (int nt = 0; nt < 2; nt++) {
                        float c4[4] = {0.f, 0.f, 0.f, 0.f};
#pragma unroll
                        for (int k = 0; k < 4; k++)
                            mma8(c4, &ar[k * 4], hB[k][nt][0], hB[k][nt][1]);
                        int eb = nt * 8 + 2 * tg;
                        float* Rw = Rwb + co_l * 36;
                        Rw[eb * 580 + mt * 16 + g]           = f2tf_f(c4[0]);
                        Rw[(eb + 1) * 580 + mt * 16 + g]     = f2tf_f(c4[1]);
                        Rw[eb * 580 + mt * 16 + g + 8]       = f2tf_f(c4[2]);
                        Rw[(eb + 1) * 580 + mt * 16 + g + 8] = f2tf_f(c4[3]);
                    }
                }
            }
            __syncthreads();

            // ---- GEMM3: out_e[co16,s16] += RW_e[co16,ci32] @ tmp_e[ci32,s16] ----
#pragma unroll
            for (int le = 0; le < 2; le++) {
                int e = wid * 2 + le;
                const float* R = sm + RW_OFF + c * RWSZ + e * 580;
                const float* T = sm + TMP_OFF + e * 580;
#pragma unroll
                for (int k = 0; k < 4; k++) {
                    uint32_t aa[4];
                    aa[0] = __float_as_uint(R[g * 36 + k * 8 + tg]);
                    aa[1] = __float_as_uint(R[(g + 8) * 36 + k * 8 + tg]);
                    aa[2] = __float_as_uint(R[g * 36 + k * 8 + tg + 4]);
                    aa[3] = __float_as_uint(R[(g + 8) * 36 + k * 8 + tg + 4]);
#pragma unroll
                    for (int nt = 0; nt < 2; nt++) {
                        uint32_t b0 = __float_as_uint(T[(nt * 8 + g) * 36 + k * 8 + tg]);
                        uint32_t b1 = __float_as_uint(T[(nt * 8 + g) * 36 + k * 8 + tg + 4]);
                        mma8(acc[le][c][nt], aa, b0, b1);
                    }
                }
            }
        }
    }

    // ---- BARRIER: all warps must finish their final GEMM3 TMP/RW reads before
    //      the epilogue scratch (stride 516, overlapping other warps' TMP rows)
    //      is written. ----
    __syncthreads();

    // ---- epilogue: acc -> smem scratch [e][co*16+s] (stride 516) -> coalesced gmem ----
#pragma unroll
    for (int le = 0; le < 2; le++) {
        float* o = sm + (wid * 2 + le) * 516;
#pragma unroll
        for (int c = 0; c < 2; c++)
#pragma unroll
            for (int nt = 0; nt < 2; nt++) {
                int co = c * 16 + g, s = nt * 8 + 2 * tg;
                o[co * 16 + s]           = acc[le][c][nt][0];
                o[co * 16 + s + 1]       = acc[le][c][nt][1];
                o[(co + 8) * 16 + s]     = acc[le][c][nt][2];
                o[(co + 8) * 16 + s + 1] = acc[le][c][nt][3];
            }
    }
    __syncthreads();
    {
        float4* dst = reinterpret_cast<float4*>(out + (size_t)e0 * 512);
#pragma unroll
        for (int j = 0; j < 8; j++) {
            int idx = t + j * 256;
            int e = idx >> 7, pos = (idx & 127) * 4;
            const float* s4 = sm + e * 516 + pos;
            dst[idx] = make_float4(s4[0], s4[1], s4[2], s4[3]);
        }
    }
}

// ---------------------------------------------------------------------------
// launch
// ---------------------------------------------------------------------------
extern "C" void kernel_launch(void* const* d_in, const int* in_sizes, int n_in,
                              void* d_out, int out_size) {
    (void)in_sizes; (void)n_in; (void)out_size;
    const float* features = (const float*)d_in[0];
    const float* edge     = (const float*)d_in[1];
    const float* basis    = (const float*)d_in[2];
    const float* w1  = (const float*)d_in[3];
    const float* b1  = (const float*)d_in[4];
    const float* g1  = (const float*)d_in[5];
    const float* be1 = (const float*)d_in[6];
    const float* w2  = (const float*)d_in[7];
    const float* b2  = (const float*)d_in[8];
    const float* g2  = (const float*)d_in[9];
    const float* be2 = (const float*)d_in[10];
    const float* w3  = (const float*)d_in[11];
    float* out = (float*)d_out;

    cudaFuncSetAttribute(conv_kernel, cudaFuncAttributeMaxDynamicSharedMemorySize, SMEM_BYTES);

    w3p_kernel<<<45056 * 32 / 256, 256>>>(w3);
    mlp_kernel<<<NE / 256, 256>>>(edge, w1, b1, g1, be1, w2, b2, g2, be2);
    conv_kernel<<<NE / 16, 256, SMEM_BYTES>>>(features, basis, out);
}

// round 17
// speedup vs baseline: 1.3159x; 1.3159x over previous
#include <cuda_runtime.h>
#include <cuda_bf16.h>
#include <stdint.h>

// Problem constants
#define NE 16384   // edges
// features [E,32,16], basis [E,16,44,16], w3 [45056,32], out [E,32,16]

// Intermediates
__device__ float g_H[NE * 32];        // radial MLP output, pre-rounded to tf32
// w3 pre-rounded to tf32, FRAGMENT-CONTIGUOUS layout:
//   idx = (((fc*16 + co_l)*2 + mt)*4 + q)*128 + lane*4 + v
//   (fc = f*2+c; co = c*16+co_l; ci = mt*16 + (v&1 ? g+8 : g);
//    m = q*8 + tg + (v&2 ? 4 : 0))
__device__ float g_w3p[45056 * 32];

// ---------------------------------------------------------------------------
// helpers
// ---------------------------------------------------------------------------
__device__ __forceinline__ uint32_t f2tf(float x) {
    uint32_t r;
    asm("cvt.rna.tf32.f32 %0, %1;" : "=r"(r) : "f"(x));
    return r;
}
__device__ __forceinline__ float f2tf_f(float x) {
    return __uint_as_float(f2tf(x));
}
__device__ __forceinline__ void mma8(float* d, const uint32_t* a, uint32_t b0, uint32_t b1) {
    asm volatile(
        "mma.sync.aligned.m16n8k8.row.col.f32.tf32.tf32.f32 "
        "{%0,%1,%2,%3}, {%4,%5,%6,%7}, {%8,%9}, {%0,%1,%2,%3};"
        : "+f"(d[0]), "+f"(d[1]), "+f"(d[2]), "+f"(d[3])
        : "r"(a[0]), "r"(a[1]), "r"(a[2]), "r"(a[3]), "r"(b0), "r"(b1));
}
__device__ __forceinline__ void cpa4(uint32_t dst, const float* src) {
    asm volatile("cp.async.ca.shared.global [%0], [%1], 4;" :: "r"(dst), "l"(src));
}
__device__ __forceinline__ uint32_t smem_u32(const void* p) {
    uint32_t a;
    asm("{ .reg .u64 t; cvta.to.shared.u64 t, %1; cvt.u32.u64 %0, t; }" : "=r"(a) : "l"(p));
    return a;
}

// ---------------------------------------------------------------------------
// Kernel 0: pre-round w3 to tf32 into the fragment-contiguous layout.
// ---------------------------------------------------------------------------
__global__ void w3p_kernel(const float* __restrict__ w3) {
    int idx  = blockIdx.x * 256 + threadIdx.x;   // 45056*32 = 1441792 total
    int v    = idx & 3;
    int lane = (idx >> 2) & 31;
    int q    = (idx >> 7) & 3;
    int mt   = (idx >> 9) & 1;
    int col  = (idx >> 10) & 15;   // co_l
    int fc   = idx >> 14;          // 0..87
    int f = fc >> 1, c = fc & 1;
    int g = lane >> 2, tg = lane & 3;
    int ci = mt * 16 + ((v & 1) ? g + 8 : g);
    int m  = q * 8 + tg + ((v & 2) ? 4 : 0);
    int co = c * 16 + col;
    g_w3p[idx] = f2tf_f(__ldg(&w3[(size_t)(co * 1408 + ci * 44 + f) * 32 + m]));
}

// ---------------------------------------------------------------------------
// Kernel 1: radial MLP (Linear->LN->ReLU->Linear->LN->ReLU) -> g_H (tf32-rounded)
// ---------------------------------------------------------------------------
__global__ void mlp_kernel(const float* __restrict__ x,
                           const float* __restrict__ w1, const float* __restrict__ b1,
                           const float* __restrict__ g1, const float* __restrict__ be1,
                           const float* __restrict__ w2, const float* __restrict__ b2,
                           const float* __restrict__ g2, const float* __restrict__ be2) {
    int e = blockIdx.x * blockDim.x + threadIdx.x;
    if (e >= NE) return;

    float xin[16];
#pragma unroll
    for (int j = 0; j < 16; j++) xin[j] = x[e * 16 + j];

    float h1[32];
#pragma unroll
    for (int m = 0; m < 32; m++) {
        float s = b1[m];
#pragma unroll
        for (int j = 0; j < 16; j++) s = fmaf(xin[j], w1[m * 16 + j], s);
        h1[m] = s;
    }
    float mu = 0.f;
#pragma unroll
    for (int m = 0; m < 32; m++) mu += h1[m];
    mu *= (1.0f / 32.0f);
    float var = 0.f;
#pragma unroll
    for (int m = 0; m < 32; m++) { float d = h1[m] - mu; var = fmaf(d, d, var); }
    var *= (1.0f / 32.0f);
    float inv = rsqrtf(var + 1e-5f);
#pragma unroll
    for (int m = 0; m < 32; m++)
        h1[m] = fmaxf((h1[m] - mu) * inv * g1[m] + be1[m], 0.0f);

    float h2[32];
#pragma unroll
    for (int m = 0; m < 32; m++) {
        float s = b2[m];
#pragma unroll
        for (int j = 0; j < 32; j++) s = fmaf(h1[j], w2[m * 32 + j], s);
        h2[m] = s;
    }
    mu = 0.f;
#pragma unroll
    for (int m = 0; m < 32; m++) mu += h2[m];
    mu *= (1.0f / 32.0f);
    var = 0.f;
#pragma unroll
    for (int m = 0; m < 32; m++) { float d = h2[m] - mu; var = fmaf(d, d, var); }
    var *= (1.0f / 32.0f);
    inv = rsqrtf(var + 1e-5f);
#pragma unroll
    for (int m = 0; m < 32; m++)
        g_H[e * 32 + m] = f2tf_f(fmaxf((h2[m] - mu) * inv * g2[m] + be2[m], 0.0f));
}

// ---------------------------------------------------------------------------
// Kernel 2: fused conv. CTA = 32 edges, 512 threads (16 warps), tf32 mma.
// cp.async double-buffered basis prefetch (full-iteration distance).
//
// smem (floats):
//   TMP [32e][16s][36ci]   @ 0      18560  (warp-private tmp; prologue/epilogue scratch)
//   RW  [32e][16co][36ci]  @ 18560  18560  (single buffer, 4 syncs/f)
//   BAS 2 x [32e][16s][20i]@ 37120  20480  (basis double buffer, conflict-free LDS)
// total 57920 floats = 231680 B (<= 232448 opt-in limit)
// ---------------------------------------------------------------------------
#define TMP_OFF 0
#define RW_OFF  18560
#define BAS_OFF 37120
#define BASSZ   10240
#define SMEM_BYTES (57920 * 4)

__global__ void __launch_bounds__(512, 1)
conv_kernel(const float* __restrict__ feat,
            const float* __restrict__ basis,
            float* __restrict__ out) {
    extern __shared__ float sm[];
    const int t    = threadIdx.x;
    const int wid  = t >> 5;
    const int lane = t & 31;
    const int g    = lane >> 2;   // 0..7
    const int tg   = lane & 3;    // 0..3
    const int e0   = blockIdx.x * 32;
    const uint32_t smb = smem_u32(sm);

    // per-thread staging coords: idx = j*512 + t -> (e, i, s), s fastest
    // src: basis[e0+e][i][f][s], dst: BAS + buf*BASSZ + e*320 + s*20 + i
    const float* basB = basis + (size_t)e0 * 11264;

    // ---- prefetch basis f=0 ----
    {
#pragma unroll
        for (int j = 0; j < 16; j++) {
            int idx = j * 512 + t;
            int s = idx & 15, i = (idx >> 4) & 15, e = idx >> 8;
            cpa4(smb + (BAS_OFF + e * 320 + s * 20 + i) * 4,
                 basB + (size_t)e * 11264 + i * 704 + s);
        }
        asm volatile("cp.async.commit_group;");
    }

    // ---- hoist H B-fragments (invariant over f and c): 32 regs ----
    uint32_t hB[4][4][2];
#pragma unroll
    for (int k = 0; k < 4; k++)
#pragma unroll
        for (int nt = 0; nt < 4; nt++) {
            hB[k][nt][0] = __float_as_uint(g_H[(size_t)(e0 + nt * 8 + g) * 32 + k * 8 + tg]);
            hB[k][nt][1] = __float_as_uint(g_H[(size_t)(e0 + nt * 8 + g) * 32 + k * 8 + tg + 4]);
        }

    // ---- stage features -> smem scratch (str-20 rows, conflict-free) ----
    // (uses TMP+RW regions only: e*640 max 20480 < 37120, does not touch BAS)
    {
        const float4* src = reinterpret_cast<const float4*>(feat + (size_t)e0 * 512);
#pragma unroll
        for (int j = 0; j < 8; j++) {
            int idx = t + j * 512;
            int e = idx >> 7, pos = (idx & 127) * 4;
            int r = pos >> 4, c0 = pos & 15;
            float4 v = src[idx];
            float* d = sm + e * 640 + r * 20 + c0;
            d[0] = v.x; d[1] = v.y; d[2] = v.z; d[3] = v.w;
        }
    }
    __syncthreads();

    // ---- hoist feature A-fragments (2 edges/warp): 32 regs ----
    uint32_t fa[2][2][2][4];   // [edge][mtile][kstep][frag]
#pragma unroll
    for (int le = 0; le < 2; le++) {
        const float* fs = sm + (wid * 2 + le) * 640;
#pragma unroll
        for (int mt = 0; mt < 2; mt++)
#pragma unroll
            for (int k = 0; k < 2; k++) {
                int r = mt * 16 + g, c = k * 8 + tg;
                fa[le][mt][k][0] = f2tf(fs[r * 20 + c]);
                fa[le][mt][k][1] = f2tf(fs[(r + 8) * 20 + c]);
                fa[le][mt][k][2] = f2tf(fs[r * 20 + c + 4]);
                fa[le][mt][k][3] = f2tf(fs[(r + 8) * 20 + c + 4]);
            }
    }

    // output accumulators: [edge][co-chunk][s-ntile][frag]
    float acc[2][2][2][4];
#pragma unroll
    for (int a = 0; a < 2; a++)
#pragma unroll
        for (int c = 0; c < 2; c++)
#pragma unroll
            for (int n = 0; n < 2; n++)
#pragma unroll
                for (int r = 0; r < 4; r++) acc[a][c][n][r] = 0.f;

#pragma unroll 1
    for (int f = 0; f < 44; f++) {
        // ---- prefetch basis f+1 into alternate buffer ----
        if (f + 1 < 44) {
            const float* bsrc = basB + (f + 1) * 16;
            uint32_t dbase = smb + (BAS_OFF + ((f + 1) & 1) * BASSZ) * 4;
#pragma unroll
            for (int j = 0; j < 16; j++) {
                int idx = j * 512 + t;
                int s = idx & 15, i = (idx >> 4) & 15, e = idx >> 8;
                cpa4(dbase + (e * 320 + s * 20 + i) * 4,
                     bsrc + (size_t)e * 11264 + i * 704 + s);
            }
            asm volatile("cp.async.commit_group;");
            asm volatile("cp.async.wait_group 1;");
        } else {
            asm volatile("cp.async.wait_group 0;");
        }
        // Barrier A: basis buf[f&1] visible to all; also fences RW reuse
        // (prev iter's c=1 GEMM3 reads) before this iter's c=0 GEMM1 writes.
        __syncthreads();

        // ---- GEMM2: tmp_f[e] = feat_e @ basis_f_e (B-fragments via LDS) ----
#pragma unroll
        for (int le = 0; le < 2; le++) {
            int e = wid * 2 + le;
            const float* bs = sm + BAS_OFF + (f & 1) * BASSZ + e * 320;
            float* tp = sm + TMP_OFF + e * 580;
#pragma unroll
            for (int nt = 0; nt < 2; nt++) {
                uint32_t bb[2][2];
#pragma unroll
                for (int k = 0; k < 2; k++) {
                    bb[k][0] = f2tf(bs[(nt * 8 + g) * 20 + k * 8 + tg]);
                    bb[k][1] = f2tf(bs[(nt * 8 + g) * 20 + k * 8 + tg + 4]);
                }
#pragma unroll
                for (int mt = 0; mt < 2; mt++) {
                    float c4[4] = {0.f, 0.f, 0.f, 0.f};
                    mma8(c4, fa[le][mt][0], bb[0][0], bb[0][1]);
                    mma8(c4, fa[le][mt][1], bb[1][0], bb[1][1]);
                    int sA = nt * 8 + 2 * tg, ciA = mt * 16 + g;
                    tp[sA * 36 + ciA]           = f2tf_f(c4[0]);
                    tp[(sA + 1) * 36 + ciA]     = f2tf_f(c4[1]);
                    tp[sA * 36 + ciA + 8]       = f2tf_f(c4[2]);
                    tp[(sA + 1) * 36 + ciA + 8] = f2tf_f(c4[3]);
                }
            }
        }

#pragma unroll
        for (int c = 0; c < 2; c++) {
            if (c == 1) __syncthreads();   // Barrier C: c=0 RW reads done before overwrite

            // ---- GEMM1: RW[co_l=wid][ci][e], A-fragments via coalesced LDG.128 ----
            const float* wb = g_w3p + (((size_t)(f * 2 + c) * 16 + wid) * 2) * 512;
            float* Rw = sm + RW_OFF + wid * 36;
#pragma unroll
            for (int mt = 0; mt < 2; mt++) {
                const float4* W4 = reinterpret_cast<const float4*>(wb + mt * 512);
                uint32_t ar[16];
#pragma unroll
                for (int q = 0; q < 4; q++) {
                    float4 v = __ldg(&W4[q * 32 + lane]);
                    ar[q * 4 + 0] = __float_as_uint(v.x);
                    ar[q * 4 + 1] = __float_as_uint(v.y);
                    ar[q * 4 + 2] = __float_as_uint(v.z);
                    ar[q * 4 + 3] = __float_as_uint(v.w);
                }
#pragma unroll
                for (int nt = 0; nt < 4; nt++) {
                    float c4[4] = {0.f, 0.f, 0.f, 0.f};
#pragma unroll
                    for (int k = 0; k < 4; k++)
                        mma8(c4, &ar[k * 4], hB[k][nt][0], hB[k][nt][1]);
                    int eb = nt * 8 + 2 * tg;
                    Rw[eb * 580 + mt * 16 + g]           = f2tf_f(c4[0]);
                    Rw[(eb + 1) * 580 + mt * 16 + g]     = f2tf_f(c4[1]);
                    Rw[eb * 580 + mt * 16 + g + 8]       = f2tf_f(c4[2]);
                    Rw[(eb + 1) * 580 + mt * 16 + g + 8] = f2tf_f(c4[3]);
                }
            }
            __syncthreads();   // Barrier B/D: RW complete before GEMM3 reads

            // ---- GEMM3: out_e[co16,s16] += RW_e[co16,ci32] @ tmp_e[ci32,s16] ----
#pragma unroll
            for (int le = 0; le < 2; le++) {
                int e = wid * 2 + le;
                const float* R = sm + RW_OFF + e * 580;
                const float* T = sm + TMP_OFF + e * 580;
#pragma unroll
                for (int k = 0; k < 4; k++) {
                    uint32_t aa[4];
                    aa[0] = __float_as_uint(R[g * 36 + k * 8 + tg]);
                    aa[1] = __float_as_uint(R[(g + 8) * 36 + k * 8 + tg]);
                    aa[2] = __float_as_uint(R[g * 36 + k * 8 + tg + 4]);
                    aa[3] = __float_as_uint(R[(g + 8) * 36 + k * 8 + tg + 4]);
#pragma unroll
                    for (int nt = 0; nt < 2; nt++) {
                        uint32_t b0 = __float_as_uint(T[(nt * 8 + g) * 36 + k * 8 + tg]);
                        uint32_t b1 = __float_as_uint(T[(nt * 8 + g) * 36 + k * 8 + tg + 4]);
                        mma8(acc[le][c][nt], aa, b0, b1);
                    }
                }
            }
        }
    }

    // ---- BARRIER: all warps done with final GEMM3 TMP/RW reads before the
    //      epilogue scratch (stride 516, overlapping other warps' TMP rows) ----
    __syncthreads();

    // ---- epilogue: acc -> smem scratch [e][co*16+s] (stride 516) -> coalesced gmem ----
#pragma unroll
    for (int le = 0; le < 2; le++) {
        float* o = sm + (wid * 2 + le) * 516;
#pragma unroll
        for (int c = 0; c < 2; c++)
#pragma unroll
            for (int nt = 0; nt < 2; nt++) {
                int co = c * 16 + g, s = nt * 8 + 2 * tg;
                o[co * 16 + s]           = acc[le][c][nt][0];
                o[co * 16 + s + 1]       = acc[le][c][nt][1];
                o[(co + 8) * 16 + s]     = acc[le][c][nt][2];
                o[(co + 8) * 16 + s + 1] = acc[le][c][nt][3];
            }
    }
    __syncthreads();
    {
        float4* dst = reinterpret_cast<float4*>(out + (size_t)e0 * 512);
#pragma unroll
        for (int j = 0; j < 8; j++) {
            int idx = t + j * 512;
            int e = idx >> 7, pos = (idx & 127) * 4;
            const float* s4 = sm + e * 516 + pos;
            dst[idx] = make_float4(s4[0], s4[1], s4[2], s4[3]);
        }
    }
}

// ---------------------------------------------------------------------------
// launch
// ---------------------------------------------------------------------------
extern "C" void kernel_launch(void* const* d_in, const int* in_sizes, int n_in,
                              void* d_out, int out_size) {
    (void)in_sizes; (void)n_in; (void)out_size;
    const float* features = (const float*)d_in[0];
    const float* edge     = (const float*)d_in[1];
    const float* basis    = (const float*)d_in[2];
    const float* w1  = (const float*)d_in[3];
    const float* b1  = (const float*)d_in[4];
    const float* g1  = (const float*)d_in[5];
    const float* be1 = (const float*)d_in[6];
    const float* w2  = (const float*)d_in[7];
    const float* b2  = (const float*)d_in[8];
    const float* g2  = (const float*)d_in[9];
    const float* be2 = (const float*)d_in[10];
    const float* w3  = (const float*)d_in[11];
    float* out = (float*)d_out;

    cudaFuncSetAttribute(conv_kernel, cudaFuncAttributeMaxDynamicSharedMemorySize, SMEM_BYTES);

    w3p_kernel<<<45056 * 32 / 256, 256>>>(w3);
    mlp_kernel<<<NE / 256, 256>>>(edge, w1, b1, g1, be1, w2, b2, g2, be2);
    conv_kernel<<<NE / 32, 512, SMEM_BYTES>>>(features, basis, out);
}